// round 8
// baseline (speedup 1.0000x reference)
#include <cuda_runtime.h>
#include <cstdint>

#define Bb 16
#define Nn 25200
#define NCc 80
#define KC 1024
#define MAXD 300
#define CONF_T 0.4f
#define IOU_T 0.25f
#define CAP 2048
#define APB 128                   // anchors per block in k1
#define K1_BYTES (APB * 85 * 4)   // 43520
#define NTASK 528                 // 32*33/2 upper-triangle chunk pairs
#define K4_SMEM (32 * 1025 * 4)   // padded row-mask matrix (131200 B dynamic smem)

// ---------------- scratch (static device globals; no allocation) ----------------
__device__ float    g_conf[Bb * Nn];
__device__ int      g_cls [Bb * Nn];
__device__ unsigned g_hist[Bb * 256];      // zeroed by k2 after use
__device__ float4   g_box [Bb * KC];
__device__ float    g_cconf[Bb * KC];
__device__ int      g_ccls[Bb * KC];
__device__ unsigned g_valid[Bb * 32];      // per-batch validity bitmap (k2)
__device__ unsigned g_rmask[Bb * 32 * KC]; // [b][colgrp w][row i]; lower triangle never written -> 0

__device__ __forceinline__ unsigned smem_u32(const void* p) {
    unsigned a;
    asm("{ .reg .u64 t; cvta.to.shared.u64 t, %1; cvt.u32.u64 %0, t; }" : "=r"(a) : "l"(p));
    return a;
}
__device__ __forceinline__ void mbar_init(unsigned m, unsigned cnt) {
    asm volatile("mbarrier.init.shared.b64 [%0], %1;" :: "r"(m), "r"(cnt) : "memory");
}
__device__ __forceinline__ void mbar_expect_tx(unsigned m, unsigned bytes) {
    asm volatile("mbarrier.arrive.expect_tx.shared.b64 _, [%0], %1;" :: "r"(m), "r"(bytes) : "memory");
}
__device__ __forceinline__ void bulk_g2s(unsigned dst, const void* src, unsigned bytes, unsigned m) {
    asm volatile("cp.async.bulk.shared::cluster.global.mbarrier::complete_tx::bytes [%0], [%1], %2, [%3];"
                 :: "r"(dst), "l"(src), "r"(bytes), "r"(m) : "memory");
}
__device__ __forceinline__ void mbar_wait(unsigned m, unsigned parity) {
    asm volatile(
        "{\n\t.reg .pred P;\n\t"
        "WL_%=:\n\t"
        "mbarrier.try_wait.parity.acquire.cta.shared::cta.b64 P, [%0], %1, 0x989680;\n\t"
        "@P bra.uni WD_%=;\n\t"
        "bra.uni WL_%=;\n\t"
        "WD_%=:\n\t}"
        :: "r"(m), "r"(parity) : "memory");
}

// ---------------- k1: TMA-staged, 1 anchor/thread, warp-uniform alignment ----------------
template<int O>
__device__ __forceinline__ void proc1(const float4* sv, float& obj, float& m, int& arg) {
    m = -1e30f; arg = 0; obj = 0.f;
    #pragma unroll
    for (int s = 1; s <= 21; s++) {
        float4 f = sv[s];
        float e[4] = {f.x, f.y, f.z, f.w};
        #pragma unroll
        for (int q = 0; q < 4; q++) {
            const int j = 4 * s + q - O;
            if (j == 4) obj = e[q];
            else if (j >= 5 && j <= 84) {
                float sc = e[q] * obj;               // exact reference op order
                if (sc > m) { m = sc; arg = j - 5; } // first-max semantics
            }
        }
    }
}

__global__ __launch_bounds__(128) void k1_scores(const float* __restrict__ pred) {
    __shared__ __align__(16) float s[APB * 85];
    __shared__ __align__(8) unsigned long long mbar;
    int t = threadIdx.x;
    int q = t >> 5, lane = t & 31;
    unsigned mb = smem_u32(&mbar);
    if (t == 0) mbar_init(mb, 1);
    __syncthreads();
    if (t == 0) {
        mbar_expect_tx(mb, K1_BYTES);
        bulk_g2s(smem_u32(s), pred + (size_t)blockIdx.x * (APB * 85), K1_BYTES, mb);
    }
    mbar_wait(mb, 0);

    int a = 4 * lane + q;                 // a%4 == q (warp-uniform alignment)
    int S = (85 * a - q) >> 2;
    const float4* sv = (const float4*)s + S;
    float obj, m; int arg;
    if      (q == 0) proc1<0>(sv, obj, m, arg);
    else if (q == 1) proc1<1>(sv, obj, m, arg);
    else if (q == 2) proc1<2>(sv, obj, m, arg);
    else             proc1<3>(sv, obj, m, arg);

    int idx = blockIdx.x * APB + a;
    int b = idx / Nn;
    bool cand = (obj > CONF_T) && (m > CONF_T);
    g_conf[idx] = cand ? m : -1.0f;
    g_cls[idx]  = arg;
    if (cand) {
        unsigned bits = __float_as_uint(m);
        int bk = (int)(bits >> 16) - 0x3ECC;
        bk = max(0, min(255, bk));
        atomicAdd(&g_hist[b * 256 + bk], 1u);
    }
}

// ---------------- k2: per-batch exact top-1024 ----------------
__global__ __launch_bounds__(1024) void k2_select(const float* __restrict__ pred) {
    __shared__ unsigned long long skeys[CAP];
    __shared__ unsigned shist[256];
    __shared__ unsigned scnt;
    __shared__ int sB1;
    int b = blockIdx.x, tid = threadIdx.x;
    if (tid == 0) { scnt = 0u; sB1 = 0; }
    if (tid < 256) {
        shist[tid] = g_hist[b * 256 + tid];
        g_hist[b * 256 + tid] = 0u;         // re-zero for next call
    }
    __syncthreads();
    #pragma unroll
    for (int off = 1; off < 256; off <<= 1) {   // suffix sum
        unsigned v = 0;
        if (tid < 256) { v = shist[tid]; if (tid + off < 256) v += shist[tid + off]; }
        __syncthreads();
        if (tid < 256) shist[tid] = v;
        __syncthreads();
    }
    if (tid < 256) {
        if (shist[tid] >= KC && (tid == 255 || shist[tid + 1] < KC)) sB1 = tid;
    }
    __syncthreads();
    int B1 = sB1;

    const float* cf = g_conf + b * Nn;
    for (int n = tid; n < Nn; n += 1024) {
        float c = cf[n];
        if (c > CONF_T) {
            unsigned bits = __float_as_uint(c);
            int bk = (int)(bits >> 16) - 0x3ECC;
            bk = max(0, min(255, bk));
            if (bk >= B1) {
                unsigned pos = atomicAdd(&scnt, 1u);
                if (pos < CAP)
                    skeys[pos] = ((unsigned long long)bits << 32) | (unsigned)(~n);
            }
        }
    }
    __syncthreads();
    unsigned tot = min(scnt, (unsigned)CAP);
    for (int i = tid; i < CAP; i += 1024)
        if ((unsigned)i >= tot) skeys[i] = 0ull;

    for (int k = 2; k <= CAP; k <<= 1) {
        for (int jj = k >> 1; jj > 0; jj >>= 1) {
            __syncthreads();
            for (int i = tid; i < CAP; i += 1024) {
                int ixj = i ^ jj;
                if (ixj > i) {
                    unsigned long long a = skeys[i], bb = skeys[ixj];
                    bool up = (i & k) == 0;
                    if (up ? (a < bb) : (a > bb)) { skeys[i] = bb; skeys[ixj] = a; }
                }
            }
        }
    }
    __syncthreads();

    unsigned long long key = skeys[tid];
    unsigned bits = (unsigned)(key >> 32);
    int n = (int)(~(unsigned)(key & 0xFFFFFFFFull));
    float conf = __uint_as_float(bits);
    float4 bx = make_float4(0.f, 0.f, 0.f, 0.f);
    int cls = 0;
    bool v0 = conf > CONF_T;
    if (v0) {
        const float* p = pred + ((size_t)b * Nn + n) * 85;
        float cx = p[0], cy = p[1], w = p[2], h = p[3];
        bx.x = cx - w * 0.5f; bx.y = cy - h * 0.5f;
        bx.z = cx + w * 0.5f; bx.w = cy + h * 0.5f;
        cls = g_cls[b * Nn + n];
    } else {
        conf = 0.0f;
    }
    g_box  [b * KC + tid] = bx;
    g_cconf[b * KC + tid] = conf;
    g_ccls [b * KC + tid] = cls;
    unsigned vb = __ballot_sync(0xffffffffu, v0);
    if ((tid & 31) == 0) g_valid[b * 32 + (tid >> 5)] = vb;
}

// ---------------- k3: IoU tiles -> row-major suppression words ----------------
__global__ __launch_bounds__(1024) void k3_iou() {
    __shared__ float4 s_box[KC];
    __shared__ float  s_area[KC];
    int b = blockIdx.y;
    int tid = threadIdx.x;
    int wid = tid >> 5, lane = tid & 31;

    float4 v = g_box[b * KC + tid];
    s_box[tid] = v;
    s_area[tid] = (v.z - v.x) * (v.w - v.y);
    __syncthreads();

    int t = blockIdx.x * 32 + wid;
    if (t < NTASK) {
        int c = 0, rm = t;
        while (rm >= 32 - c) { rm -= 32 - c; c++; }
        int wcol = c + rm;

        float4 ri = s_box[c * 32 + lane];
        float ra = s_area[c * 32 + lane];
        unsigned myword = 0;
        #pragma unroll 4
        for (int jj = 0; jj < 32; jj++) {
            int col = wcol * 32 + jj;
            float4 cb = s_box[col];
            float aj = s_area[col];
            float ltx = fmaxf(ri.x, cb.x), lty = fmaxf(ri.y, cb.y);
            float rx  = fminf(ri.z, cb.z), ry  = fminf(ri.w, cb.w);
            float ww = fmaxf(rx - ltx, 0.f), hh = fmaxf(ry - lty, 0.f);
            float inter = ww * hh;
            float d = ra + aj - inter + 1e-9f;
            float diff = fmaf(-IOU_T, d, inter);
            bool sup;
            bool near = fabsf(diff) < 1e-4f * d;
            if (__any_sync(0xffffffffu, near)) {
                sup = (inter / d) > IOU_T;           // exact reference path (rare)
            } else {
                sup = diff > 0.0f;
            }
            unsigned bal = __ballot_sync(0xffffffffu, sup);
            if (lane == jj) myword = bal;            // col word: bits = rows
        }
        // 32x32 bit transpose across lanes: -> lane = row, bits = cols
        unsigned x = myword;
        const unsigned LM[5] = {0x0000FFFFu, 0x00FF00FFu, 0x0F0F0F0Fu, 0x33333333u, 0x55555555u};
        #pragma unroll
        for (int si = 0; si < 5; si++) {
            int s2 = 16 >> si;
            unsigned L = LM[si];
            unsigned y = __shfl_xor_sync(0xffffffffu, x, s2);
            x = (lane & s2) ? ((x & ~L) | ((y & ~L) >> s2))
                            : ((x & L) | ((y & L) << s2));
        }
        if (wcol == c) x &= (0xFFFFFFFEu << lane);   // diagonal: only cols > row
        g_rmask[(b * 32 + wcol) * KC + c * 32 + lane] = x;   // coalesced
    }
}

// ---------------- k4: warp-serial greedy NMS over smem bitset + outputs ----------------
__global__ __launch_bounds__(256) void k4_nms(const int* __restrict__ pimg,
                                              float* __restrict__ out) {
    extern __shared__ unsigned srm[];       // [32][1025] padded
    __shared__ unsigned keptw[32];
    __shared__ int spfx[33];
    int b = blockIdx.x, tid = threadIdx.x;
    int lane = tid & 31, warp = tid >> 5;

    const unsigned* src = g_rmask + (size_t)b * 32 * KC;
    for (int idx = tid; idx < 32 * KC; idx += 256) {
        int w = idx >> 10, i = idx & 1023;
        srm[w * 1025 + i] = src[idx];
    }
    __syncthreads();

    if (warp == 0) {
        unsigned rem = g_valid[b * 32 + lane];   // cols [32*lane, +32)
        unsigned kept = 0;
        while (true) {
            unsigned anyb = __ballot_sync(0xffffffffu, rem != 0);
            if (!anyb) break;
            int g0 = __ffs(anyb) - 1;
            unsigned rg = __shfl_sync(0xffffffffu, rem, g0);
            int bit = __ffs(rg) - 1;
            int i = g0 * 32 + bit;               // lowest remaining index -> kept (greedy order)
            if (lane == g0) { kept |= 1u << bit; rem &= ~(1u << bit); }
            rem &= ~srm[lane * 1025 + i];        // remove its victims (row i, only j>i set)
        }
        keptw[lane] = kept;
        int pfx = __popc(kept);
        #pragma unroll
        for (int s = 1; s < 32; s <<= 1) {
            int y = __shfl_up_sync(0xffffffffu, pfx, s);
            if (lane >= s) pfx += y;
        }
        spfx[lane + 1] = pfx;
        if (lane == 0) spfx[0] = 0;
    }
    __syncthreads();
    int nk = spfx[32];

    float* dets  = out;
    float* valid = out + Bb * MAXD * 6;
    float* feats = out + Bb * MAXD * 6 + Bb * MAXD;

    float fimg = 640.0f;
    if (pimg) {
        int iv = *pimg;
        fimg = (iv > 0 && iv < (1 << 20)) ? (float)iv : __int_as_float(iv);
    }
    float scale = 1.0f / fimg;

    for (int r = tid; r < MAXD; r += 256) {
        bool v = r < nk;
        if (!v) {
            #pragma unroll
            for (int q = 0; q < 6; q++) dets[((size_t)b * MAXD + r) * 6 + q] = 0.f;
        }
        valid[b * MAXD + r] = v ? 1.0f : 0.0f;
    }
    if (b == 0) {
        for (int i = tid; i < MAXD * (NCc + 2); i += 256) feats[i] = 0.f;
    }
    __syncthreads();

    for (int j = tid; j < KC; j += 256) {
        unsigned kw = keptw[j >> 5];
        if ((kw >> (j & 31)) & 1u) {
            int rank = spfx[j >> 5] + __popc(kw & ((1u << (j & 31)) - 1u));
            if (rank < MAXD) {
                float4 bx = g_box[b * KC + j];
                float conf = g_cconf[b * KC + j];
                int cls = g_ccls[b * KC + j];
                float* dr = dets + ((size_t)b * MAXD + rank) * 6;
                dr[0] = bx.x; dr[1] = bx.y; dr[2] = bx.z; dr[3] = bx.w;
                dr[4] = conf; dr[5] = (float)cls;
                if (b == 0) {
                    float cx = (bx.x + bx.z) * 0.5f * scale;
                    float cy = (bx.y + bx.w) * 0.5f * scale;
                    feats[rank * (NCc + 2) + 0] = cx;
                    feats[rank * (NCc + 2) + 1] = cy;
                    feats[rank * (NCc + 2) + 2 + cls] = 1.0f;
                }
            }
        }
    }
}

// ---------------- launch ----------------
extern "C" void kernel_launch(void* const* d_in, const int* in_sizes, int n_in,
                              void* d_out, int out_size) {
    const float* pred = (const float*)d_in[0];
    const int* pimg = (n_in >= 2) ? (const int*)d_in[1] : nullptr;
    float* out = (float*)d_out;

    // unconditional (no static guards per harness rules); idempotent, host-side only
    cudaFuncSetAttribute(k4_nms, cudaFuncAttributeMaxDynamicSharedMemorySize, K4_SMEM);

    k1_scores<<<(Bb * Nn) / APB, 128>>>(pred);
    k2_select<<<Bb, 1024>>>(pred);
    k3_iou<<<dim3(17, Bb), 1024>>>();
    k4_nms<<<Bb, 256, K4_SMEM>>>(pimg, out);
}

// round 9
// speedup vs baseline: 1.3122x; 1.3122x over previous
#include <cuda_runtime.h>
#include <cstdint>

#define Bb 16
#define Nn 25200
#define NCc 80
#define KC 1024
#define MAXD 300
#define CONF_T 0.4f
#define IOU_T 0.25f
#define CAP 2048
#define APB 128                   // anchors per block in k1
#define K1_BYTES (APB * 85 * 4)   // 43520
#define NTASK 528                 // 32*33/2 upper-triangle chunk pairs

// ---------------- scratch (static device globals; no allocation) ----------------
__device__ float    g_conf[Bb * Nn];
__device__ int      g_cls [Bb * Nn];
__device__ unsigned g_hist[Bb * 256];      // zeroed by k2 after use
__device__ float4   g_box [Bb * KC];
__device__ float    g_cconf[Bb * KC];
__device__ int      g_ccls[Bb * KC];
__device__ unsigned g_valid[Bb * 32];      // per-batch validity bitmap (k2)
__device__ unsigned g_mask[Bb * 32 * KC];  // col-major: [b][rowchunk c][col j], bits=rows, only i<j;
                                            // lower triangle never written -> stays 0
__device__ unsigned g_diag[Bb * 32 * 32];  // row-major diagonal tiles: [b][c][row b'], bits=cols>row

__device__ __forceinline__ unsigned smem_u32(const void* p) {
    unsigned a;
    asm("{ .reg .u64 t; cvta.to.shared.u64 t, %1; cvt.u32.u64 %0, t; }" : "=r"(a) : "l"(p));
    return a;
}
__device__ __forceinline__ void mbar_init(unsigned m, unsigned cnt) {
    asm volatile("mbarrier.init.shared.b64 [%0], %1;" :: "r"(m), "r"(cnt) : "memory");
}
__device__ __forceinline__ void mbar_expect_tx(unsigned m, unsigned bytes) {
    asm volatile("mbarrier.arrive.expect_tx.shared.b64 _, [%0], %1;" :: "r"(m), "r"(bytes) : "memory");
}
__device__ __forceinline__ void bulk_g2s(unsigned dst, const void* src, unsigned bytes, unsigned m) {
    asm volatile("cp.async.bulk.shared::cluster.global.mbarrier::complete_tx::bytes [%0], [%1], %2, [%3];"
                 :: "r"(dst), "l"(src), "r"(bytes), "r"(m) : "memory");
}
__device__ __forceinline__ void mbar_wait(unsigned m, unsigned parity) {
    asm volatile(
        "{\n\t.reg .pred P;\n\t"
        "WL_%=:\n\t"
        "mbarrier.try_wait.parity.acquire.cta.shared::cta.b64 P, [%0], %1, 0x989680;\n\t"
        "@P bra.uni WD_%=;\n\t"
        "bra.uni WL_%=;\n\t"
        "WD_%=:\n\t}"
        :: "r"(m), "r"(parity) : "memory");
}

// ---------------- k1: TMA-staged, 1 anchor/thread, warp-uniform alignment ----------------
template<int O>
__device__ __forceinline__ void proc1(const float4* sv, float& obj, float& m, int& arg) {
    m = -1e30f; arg = 0; obj = 0.f;
    #pragma unroll
    for (int s = 1; s <= 21; s++) {
        float4 f = sv[s];
        float e[4] = {f.x, f.y, f.z, f.w};
        #pragma unroll
        for (int q = 0; q < 4; q++) {
            const int j = 4 * s + q - O;
            if (j == 4) obj = e[q];
            else if (j >= 5 && j <= 84) {
                float sc = e[q] * obj;               // exact reference op order
                if (sc > m) { m = sc; arg = j - 5; } // first-max semantics
            }
        }
    }
}

__global__ __launch_bounds__(128) void k1_scores(const float* __restrict__ pred) {
    __shared__ __align__(16) float s[APB * 85];
    __shared__ __align__(8) unsigned long long mbar;
    int t = threadIdx.x;
    int q = t >> 5, lane = t & 31;
    unsigned mb = smem_u32(&mbar);
    if (t == 0) mbar_init(mb, 1);
    __syncthreads();
    if (t == 0) {
        mbar_expect_tx(mb, K1_BYTES);
        bulk_g2s(smem_u32(s), pred + (size_t)blockIdx.x * (APB * 85), K1_BYTES, mb);
    }
    mbar_wait(mb, 0);

    int a = 4 * lane + q;                 // a%4 == q (warp-uniform alignment)
    int S = (85 * a - q) >> 2;
    const float4* sv = (const float4*)s + S;
    float obj, m; int arg;
    if      (q == 0) proc1<0>(sv, obj, m, arg);
    else if (q == 1) proc1<1>(sv, obj, m, arg);
    else if (q == 2) proc1<2>(sv, obj, m, arg);
    else             proc1<3>(sv, obj, m, arg);

    int idx = blockIdx.x * APB + a;
    int b = idx / Nn;
    bool cand = (obj > CONF_T) && (m > CONF_T);
    g_conf[idx] = cand ? m : -1.0f;
    g_cls[idx]  = arg;
    if (cand) {
        unsigned bits = __float_as_uint(m);
        int bk = (int)(bits >> 16) - 0x3ECC;
        bk = max(0, min(255, bk));
        atomicAdd(&g_hist[b * 256 + bk], 1u);
    }
}

// ---------------- k2: per-batch exact top-1024 ----------------
__global__ __launch_bounds__(1024) void k2_select(const float* __restrict__ pred) {
    __shared__ unsigned long long skeys[CAP];
    __shared__ unsigned shist[256];
    __shared__ unsigned scnt;
    __shared__ int sB1;
    int b = blockIdx.x, tid = threadIdx.x;
    if (tid == 0) { scnt = 0u; sB1 = 0; }
    if (tid < 256) {
        shist[tid] = g_hist[b * 256 + tid];
        g_hist[b * 256 + tid] = 0u;         // re-zero for next call
    }
    __syncthreads();
    #pragma unroll
    for (int off = 1; off < 256; off <<= 1) {   // suffix sum
        unsigned v = 0;
        if (tid < 256) { v = shist[tid]; if (tid + off < 256) v += shist[tid + off]; }
        __syncthreads();
        if (tid < 256) shist[tid] = v;
        __syncthreads();
    }
    if (tid < 256) {
        if (shist[tid] >= KC && (tid == 255 || shist[tid + 1] < KC)) sB1 = tid;
    }
    __syncthreads();
    int B1 = sB1;

    const float* cf = g_conf + b * Nn;
    for (int n = tid; n < Nn; n += 1024) {
        float c = cf[n];
        if (c > CONF_T) {
            unsigned bits = __float_as_uint(c);
            int bk = (int)(bits >> 16) - 0x3ECC;
            bk = max(0, min(255, bk));
            if (bk >= B1) {
                unsigned pos = atomicAdd(&scnt, 1u);
                if (pos < CAP)
                    skeys[pos] = ((unsigned long long)bits << 32) | (unsigned)(~n);
            }
        }
    }
    __syncthreads();
    unsigned tot = min(scnt, (unsigned)CAP);
    for (int i = tid; i < CAP; i += 1024)
        if ((unsigned)i >= tot) skeys[i] = 0ull;

    for (int k = 2; k <= CAP; k <<= 1) {
        for (int jj = k >> 1; jj > 0; jj >>= 1) {
            __syncthreads();
            for (int i = tid; i < CAP; i += 1024) {
                int ixj = i ^ jj;
                if (ixj > i) {
                    unsigned long long a = skeys[i], bb = skeys[ixj];
                    bool up = (i & k) == 0;
                    if (up ? (a < bb) : (a > bb)) { skeys[i] = bb; skeys[ixj] = a; }
                }
            }
        }
    }
    __syncthreads();

    unsigned long long key = skeys[tid];
    unsigned bits = (unsigned)(key >> 32);
    int n = (int)(~(unsigned)(key & 0xFFFFFFFFull));
    float conf = __uint_as_float(bits);
    float4 bx = make_float4(0.f, 0.f, 0.f, 0.f);
    int cls = 0;
    bool v0 = conf > CONF_T;
    if (v0) {
        const float* p = pred + ((size_t)b * Nn + n) * 85;
        float cx = p[0], cy = p[1], w = p[2], h = p[3];
        bx.x = cx - w * 0.5f; bx.y = cy - h * 0.5f;
        bx.z = cx + w * 0.5f; bx.w = cy + h * 0.5f;
        cls = g_cls[b * Nn + n];
    } else {
        conf = 0.0f;
    }
    g_box  [b * KC + tid] = bx;
    g_cconf[b * KC + tid] = conf;
    g_ccls [b * KC + tid] = cls;
    unsigned vb = __ballot_sync(0xffffffffu, v0);
    if ((tid & 31) == 0) g_valid[b * 32 + (tid >> 5)] = vb;
}

// ---------------- k3: IoU tiles -> col-major words (+ row-major diagonal) ----------------
__global__ __launch_bounds__(1024) void k3_iou() {
    __shared__ float4 s_box[KC];
    __shared__ float  s_area[KC];
    int b = blockIdx.y;
    int tid = threadIdx.x;
    int wid = tid >> 5, lane = tid & 31;

    float4 v = g_box[b * KC + tid];
    s_box[tid] = v;
    s_area[tid] = (v.z - v.x) * (v.w - v.y);
    __syncthreads();

    int t = blockIdx.x * 32 + wid;
    if (t < NTASK) {
        int c = 0, rm = t;
        while (rm >= 32 - c) { rm -= 32 - c; c++; }
        int wcol = c + rm;

        float4 ri = s_box[c * 32 + lane];
        float ra = s_area[c * 32 + lane];
        unsigned myword = 0;
        #pragma unroll 4
        for (int jj = 0; jj < 32; jj++) {
            int col = wcol * 32 + jj;
            float4 cb = s_box[col];
            float aj = s_area[col];
            float ltx = fmaxf(ri.x, cb.x), lty = fmaxf(ri.y, cb.y);
            float rx  = fminf(ri.z, cb.z), ry  = fminf(ri.w, cb.w);
            float ww = fmaxf(rx - ltx, 0.f), hh = fmaxf(ry - lty, 0.f);
            float inter = ww * hh;
            float d = ra + aj - inter + 1e-9f;
            float diff = fmaf(-IOU_T, d, inter);
            bool sup;
            bool near = fabsf(diff) < 1e-4f * d;
            if (__any_sync(0xffffffffu, near)) {
                sup = (inter / d) > IOU_T;           // exact reference path (rare)
            } else {
                sup = diff > 0.0f;
            }
            unsigned bal = __ballot_sync(0xffffffffu, sup);
            unsigned cm = (wcol > c) ? 0xffffffffu : ((jj == 0) ? 0u : ((1u << jj) - 1u));
            if (lane == jj) myword = bal & cm;       // col word, bits=rows, only i<j
        }
        g_mask[(b * 32 + c) * KC + wcol * 32 + lane] = myword;

        if (wcol == c) {
            // 32x32 bit transpose: -> lane = row, bits = cols (>row only, from cm mask)
            unsigned x = myword;
            const unsigned LM[5] = {0x0000FFFFu, 0x00FF00FFu, 0x0F0F0F0Fu, 0x33333333u, 0x55555555u};
            #pragma unroll
            for (int si = 0; si < 5; si++) {
                int s2 = 16 >> si;
                unsigned L = LM[si];
                unsigned y = __shfl_xor_sync(0xffffffffu, x, s2);
                x = (lane & s2) ? ((x & ~L) | ((y & ~L) >> s2))
                                : ((x & L) | ((y & L) << s2));
            }
            g_diag[(b * 32 + c) * 32 + lane] = x;
        }
    }
}

// ---------------- k4: chunk-pipeline NMS (prefetched words + bit-serial closure) ----------------
__global__ __launch_bounds__(1024) void k4_nms(const int* __restrict__ pimg,
                                               float* __restrict__ out) {
    __shared__ unsigned sdiag[32 * 32];
    __shared__ unsigned skept[32];
    __shared__ int spfx[33];
    int b = blockIdx.x, j = threadIdx.x;
    int lane = j & 31, warp = j >> 5;

    sdiag[j] = g_diag[b * KC + j];                 // 1024 words, one per thread
    bool alive = (g_valid[b * 32 + warp] >> lane) & 1u;

    const unsigned* gm = g_mask + (size_t)b * 32 * KC;
    unsigned wload = gm[j];                        // chunk 0 column word
    unsigned wuse = 0;
    __syncthreads();

    #pragma unroll 1
    for (int c = 0; c < 32; c++) {
        if (c > 0) alive = alive && !(wuse & skept[c - 1]);   // harmless for finalized cols
        wuse = wload;
        if (c < 31) wload = gm[(c + 1) * KC + j];  // prefetch next chunk (L2), hidden by resolve
        if (warp == c) {
            unsigned R[32];
            #pragma unroll
            for (int bb = 0; bb < 32; bb++) R[bb] = sdiag[c * 32 + bb];  // broadcast LDS
            unsigned rem = __ballot_sync(0xffffffffu, alive);
            unsigned kept = 0;
            #pragma unroll
            for (int bb = 0; bb < 32; bb++) {      // bit-serial greedy closure (~4cyc/step)
                if ((rem >> bb) & 1u) { kept |= 1u << bb; rem &= ~R[bb]; }
            }
            alive = alive && ((kept >> lane) & 1u);
            if (lane == 0) skept[c] = kept;
        }
        __syncthreads();
    }

    if (warp == 0) {
        int pfx = __popc(skept[lane]);
        #pragma unroll
        for (int s = 1; s < 32; s <<= 1) {
            int y = __shfl_up_sync(0xffffffffu, pfx, s);
            if (lane >= s) pfx += y;
        }
        spfx[lane + 1] = pfx;
        if (lane == 0) spfx[0] = 0;
    }
    __syncthreads();
    int nk = spfx[32];

    float* dets  = out;
    float* valid = out + Bb * MAXD * 6;
    float* feats = out + Bb * MAXD * 6 + Bb * MAXD;

    float fimg = 640.0f;
    if (pimg) {
        int iv = *pimg;
        fimg = (iv > 0 && iv < (1 << 20)) ? (float)iv : __int_as_float(iv);
    }
    float scale = 1.0f / fimg;

    if (j < MAXD) {
        bool v = j < nk;
        if (!v) {
            #pragma unroll
            for (int q = 0; q < 6; q++) dets[((size_t)b * MAXD + j) * 6 + q] = 0.f;
        }
        valid[b * MAXD + j] = v ? 1.0f : 0.0f;
    }
    if (b == 0) {
        for (int i = j; i < MAXD * (NCc + 2); i += 1024) feats[i] = 0.f;
    }
    __syncthreads();

    unsigned kw = skept[warp];
    if ((kw >> lane) & 1u) {
        int rank = spfx[warp] + __popc(kw & ((1u << lane) - 1u));
        if (rank < MAXD) {
            float4 bx = g_box[b * KC + j];
            float conf = g_cconf[b * KC + j];
            int cls = g_ccls[b * KC + j];
            float* dr = dets + ((size_t)b * MAXD + rank) * 6;
            dr[0] = bx.x; dr[1] = bx.y; dr[2] = bx.z; dr[3] = bx.w;
            dr[4] = conf; dr[5] = (float)cls;
            if (b == 0) {
                float cx = (bx.x + bx.z) * 0.5f * scale;
                float cy = (bx.y + bx.w) * 0.5f * scale;
                feats[rank * (NCc + 2) + 0] = cx;
                feats[rank * (NCc + 2) + 1] = cy;
                feats[rank * (NCc + 2) + 2 + cls] = 1.0f;
            }
        }
    }
}

// ---------------- launch ----------------
extern "C" void kernel_launch(void* const* d_in, const int* in_sizes, int n_in,
                              void* d_out, int out_size) {
    const float* pred = (const float*)d_in[0];
    const int* pimg = (n_in >= 2) ? (const int*)d_in[1] : nullptr;
    float* out = (float*)d_out;

    k1_scores<<<(Bb * Nn) / APB, 128>>>(pred);
    k2_select<<<Bb, 1024>>>(pred);
    k3_iou<<<dim3(17, Bb), 1024>>>();
    k4_nms<<<Bb, 1024>>>(pimg, out);
}